// round 6
// baseline (speedup 1.0000x reference)
#include <cuda_runtime.h>

// Problem constants
#define A_N 2048
#define D_N 64
#define F_N 12
#define K_N (A_N * F_N)   // 24576
#define C_N 66            // D + 2
#define GN  (F_N * D_N)   // 768 = columns of W-matrix view

// Split-K config for the big GEMM: 16 M-tiles x 9 K-splits = 144 CTAs (one wave on 148 SMs)
#define NSPLIT 9
#define KCHUNK 2736       // 8*2736 + 2688 = 24576, both multiples of BK=16

// ---------------------------------------------------------------------------
// Scratch (device globals only — no allocation allowed)
// ---------------------------------------------------------------------------
__device__ float g_G[2][D_N * GN];          // G[fi][d][f*64+o] = filt_fi[o][f][d]
__device__ float g_bt[2][A_N * D_N];        // bond term per filter (x-independent)
__device__ float g_W[K_N * D_N];            // W[k][o], k = n*12+f  (== x @ G, row-major 2048x768)
__device__ float g_xa[A_N * D_N];           // activation ping
__device__ float g_xb[A_N * D_N];           // activation pong
__device__ float g_part[NSPLIT][A_N * D_N]; // split-K partials

// ---------------------------------------------------------------------------
// Packed fp32x2 helpers (Blackwell: 2x fp32 FMA throughput; ptxas won't auto-fuse)
// ---------------------------------------------------------------------------
__device__ __forceinline__ unsigned long long pack2(float x, float y) {
    unsigned long long r;
    asm("mov.b64 %0, {%1, %2};" : "=l"(r) : "f"(x), "f"(y));
    return r;
}
__device__ __forceinline__ void unpack2(unsigned long long v, float &lo, float &hi) {
    asm("mov.b64 {%0, %1}, %2;" : "=f"(lo), "=f"(hi) : "l"(v));
}
__device__ __forceinline__ void ffma2(unsigned long long &acc, unsigned long long a,
                                      unsigned long long b) {
    asm("fma.rn.f32x2 %0, %1, %2, %0;" : "+l"(acc) : "l"(a), "l"(b));
}

// ---------------------------------------------------------------------------
// Prep: transpose filters into G  (G[fi][d*768 + f*64 + o] = filt[o*792 + f*66 + d])
// ---------------------------------------------------------------------------
__global__ void prep_g_kernel(const float* __restrict__ f0, const float* __restrict__ f1) {
    int i = blockIdx.x * blockDim.x + threadIdx.x;
    if (i >= 2 * D_N * GN) return;
    int fi = i / (D_N * GN);
    int r  = i % (D_N * GN);
    int d  = r / GN;
    int j  = r % GN;          // j = f*64 + o
    int f  = j >> 6;
    int o  = j & 63;
    const float* filt = fi ? f1 : f0;
    g_G[fi][r] = filt[(o * F_N + f) * C_N + d];
}

// Prep: bond term  bt[fi][a][o] = sum_f bond[a,f,0]*filt[o,f,64] + bond[a,f,1]*filt[o,f,65]
__global__ void prep_bt_kernel(const float* __restrict__ bond,
                               const float* __restrict__ f0,
                               const float* __restrict__ f1) {
    int i = blockIdx.x * blockDim.x + threadIdx.x;
    if (i >= 2 * A_N * D_N) return;
    int fi = i / (A_N * D_N);
    int r  = i % (A_N * D_N);
    int a  = r / D_N;
    int o  = r % D_N;
    const float* filt = fi ? f1 : f0;
    float s = 0.f;
#pragma unroll
    for (int f = 0; f < F_N; ++f) {
        s += bond[(a * F_N + f) * 2 + 0] * filt[(o * F_N + f) * C_N + 64];
        s += bond[(a * F_N + f) * 2 + 1] * filt[(o * F_N + f) * C_N + 65];
    }
    g_bt[fi][r] = s;
}

// ---------------------------------------------------------------------------
// W GEMM:  W(2048 x 768) = X(2048 x 64) @ G(64 x 768)
// Block: 64(M) x 128(N), 256 threads, full K=64 in smem. grid (32, 6).
// xsel: 0 -> g_xa, 1 -> g_xb, else external pointer.
// ---------------------------------------------------------------------------
__global__ void __launch_bounds__(256) wgemm_kernel(const float* __restrict__ xext,
                                                    int xsel, int fi) {
    const float* X = (xsel == 0) ? g_xa : (xsel == 1) ? g_xb : xext;
    const float* G = g_G[fi];

    __shared__ float xs[64][68];   // xs[k][m], padded
    __shared__ float gs[64][128];  // gs[k][n]

    int tid = threadIdx.x;
    int m0 = blockIdx.x * 64;
    int j0 = blockIdx.y * 128;

    // Load X tile (64 rows x 64 k), transpose into xs[k][m]
    for (int i = tid; i < 64 * 16; i += 256) {   // 1024 float4
        int row = i >> 4;
        int kq  = i & 15;
        float4 v = *(const float4*)&X[(size_t)(m0 + row) * D_N + kq * 4];
        xs[kq * 4 + 0][row] = v.x;
        xs[kq * 4 + 1][row] = v.y;
        xs[kq * 4 + 2][row] = v.z;
        xs[kq * 4 + 3][row] = v.w;
    }
    // Load G tile (64 x 128) directly
    for (int i = tid; i < 64 * 32; i += 256) {   // 2048 float4
        int d  = i >> 5;
        int cq = i & 31;
        *(float4*)&gs[d][cq * 4] = *(const float4*)&G[(size_t)d * GN + j0 + cq * 4];
    }
    __syncthreads();

    int tx = tid & 31;   // n: tx*4
    int ty = tid >> 5;   // m: ty*8 .. +7
    float acc[8][4];
#pragma unroll
    for (int im = 0; im < 8; ++im)
#pragma unroll
        for (int jn = 0; jn < 4; ++jn) acc[im][jn] = 0.f;

#pragma unroll 4
    for (int k = 0; k < 64; ++k) {
        float4 a0 = *(const float4*)&xs[k][ty * 8];
        float4 a1 = *(const float4*)&xs[k][ty * 8 + 4];
        float4 b  = *(const float4*)&gs[k][tx * 4];
        float av[8] = {a0.x, a0.y, a0.z, a0.w, a1.x, a1.y, a1.z, a1.w};
        float bv[4] = {b.x, b.y, b.z, b.w};
#pragma unroll
        for (int im = 0; im < 8; ++im)
#pragma unroll
            for (int jn = 0; jn < 4; ++jn) acc[im][jn] += av[im] * bv[jn];
    }

#pragma unroll
    for (int im = 0; im < 8; ++im) {
        size_t row = (size_t)(m0 + ty * 8 + im);
        *(float4*)&g_W[row * GN + j0 + tx * 4] =
            make_float4(acc[im][0], acc[im][1], acc[im][2], acc[im][3]);
    }
}

// ---------------------------------------------------------------------------
// Big GEMM (split-K):  part[s] += conn(2048 x 24576) @ W(24576 x 64)  for k-slice s
// BM=128, BN=64, BK=16, 256 threads, f32x2 packed FMAs. grid (16, 9).
// ---------------------------------------------------------------------------
__global__ void __launch_bounds__(256, 1) big_gemm_kernel(const float* __restrict__ conn) {
    __shared__ float As[16][132];   // As[kk][m], padded
    __shared__ float Bs[16][64];    // Bs[kk][n]

    int tid   = threadIdx.x;
    int mbase = blockIdx.x * 128;
    int s     = blockIdx.y;
    int k0    = s * KCHUNK;
    int klen  = min(KCHUNK, K_N - k0);
    int niter = klen >> 4;

    // compute-thread mapping: 16x16 threads, thread tile 8m x 4n
    int tx = tid & 15, ty = tid >> 4;
    const int mo0 = ty * 4;
    const int mo1 = ty * 4 + 64;
    const int no  = tx * 4;

    // acc[mpair][n]: mpair 0=(mo0,mo0+1) 1=(mo0+2,mo0+3) 2=(mo1,mo1+1) 3=(mo1+2,mo1+3)
    unsigned long long acc[4][4];
#pragma unroll
    for (int p = 0; p < 4; ++p)
#pragma unroll
        for (int n = 0; n < 4; ++n) acc[p][n] = 0ULL;

    // A loader mapping: element i in [0,512) float4s: row=i>>2, kseg=i&3
    const int arow = tid >> 2;
    const int kcol = (tid & 3) * 4;
    const float* aptr0 = conn + (size_t)(mbase + arow) * K_N + k0 + kcol;
    const float* aptr1 = aptr0 + (size_t)64 * K_N;

    // B loader mapping: kkb in 0..3, ob in 0..63; covers kk = kkb + 4p
    const int kkb = tid >> 6;
    const int ob  = tid & 63;

    float4 aR0 = *(const float4*)(aptr0);
    float4 aR1 = *(const float4*)(aptr1);
    float  bR[4];
#pragma unroll
    for (int p = 0; p < 4; ++p) bR[p] = g_W[(size_t)(k0 + kkb + p * 4) * D_N + ob];

    for (int it = 0; it < niter; ++it) {
        // stage -> smem
        As[kcol + 0][arow]      = aR0.x;
        As[kcol + 1][arow]      = aR0.y;
        As[kcol + 2][arow]      = aR0.z;
        As[kcol + 3][arow]      = aR0.w;
        As[kcol + 0][arow + 64] = aR1.x;
        As[kcol + 1][arow + 64] = aR1.y;
        As[kcol + 2][arow + 64] = aR1.z;
        As[kcol + 3][arow + 64] = aR1.w;
#pragma unroll
        for (int p = 0; p < 4; ++p) Bs[kkb + p * 4][ob] = bR[p];
        __syncthreads();

        // prefetch next tile into registers
        if (it + 1 < niter) {
            int koff = (it + 1) * 16;
            aR0 = *(const float4*)(aptr0 + koff);
            aR1 = *(const float4*)(aptr1 + koff);
#pragma unroll
            for (int p = 0; p < 4; ++p)
                bR[p] = g_W[(size_t)(k0 + koff + kkb + p * 4) * D_N + ob];
        }

        // compute 16 k-steps
#pragma unroll
        for (int kk = 0; kk < 16; ++kk) {
            float4 a0 = *(const float4*)&As[kk][mo0];
            float4 a1 = *(const float4*)&As[kk][mo1];
            float4 b  = *(const float4*)&Bs[kk][no];
            unsigned long long ap0 = pack2(a0.x, a0.y);
            unsigned long long ap1 = pack2(a0.z, a0.w);
            unsigned long long ap2 = pack2(a1.x, a1.y);
            unsigned long long ap3 = pack2(a1.z, a1.w);
            unsigned long long bb0 = pack2(b.x, b.x);
            unsigned long long bb1 = pack2(b.y, b.y);
            unsigned long long bb2 = pack2(b.z, b.z);
            unsigned long long bb3 = pack2(b.w, b.w);
            ffma2(acc[0][0], ap0, bb0); ffma2(acc[0][1], ap0, bb1);
            ffma2(acc[0][2], ap0, bb2); ffma2(acc[0][3], ap0, bb3);
            ffma2(acc[1][0], ap1, bb0); ffma2(acc[1][1], ap1, bb1);
            ffma2(acc[1][2], ap1, bb2); ffma2(acc[1][3], ap1, bb3);
            ffma2(acc[2][0], ap2, bb0); ffma2(acc[2][1], ap2, bb1);
            ffma2(acc[2][2], ap2, bb2); ffma2(acc[2][3], ap2, bb3);
            ffma2(acc[3][0], ap3, bb0); ffma2(acc[3][1], ap3, bb1);
            ffma2(acc[3][2], ap3, bb2); ffma2(acc[3][3], ap3, bb3);
        }
        __syncthreads();
    }

    // write partials (float4 per output row)
    float* outp = &g_part[s][0];
#pragma unroll
    for (int p = 0; p < 4; ++p) {
        int m = (p < 2) ? (mo0 + p * 2) : (mo1 + (p - 2) * 2);
        float lo[4], hi[4];
#pragma unroll
        for (int n = 0; n < 4; ++n) unpack2(acc[p][n], lo[n], hi[n]);
        *(float4*)&outp[(size_t)(mbase + m) * D_N + no] =
            make_float4(lo[0], lo[1], lo[2], lo[3]);
        *(float4*)&outp[(size_t)(mbase + m + 1) * D_N + no] =
            make_float4(hi[0], hi[1], hi[2], hi[3]);
    }
}

// ---------------------------------------------------------------------------
// Reduce split-K partials + epilogue (bond term [+ residual] + ReLU)
// osel: 0 -> g_xa, 1 -> g_xb, else external (d_out)
// ---------------------------------------------------------------------------
__global__ void reduce_kernel(const float* __restrict__ xres, int fi,
                              float* __restrict__ oext, int osel) {
    int i = blockIdx.x * blockDim.x + threadIdx.x;
    if (i >= A_N * D_N) return;
    float acc = g_bt[fi][i];
#pragma unroll
    for (int p = 0; p < NSPLIT; ++p) acc += g_part[p][i];
    if (xres) acc += xres[i];
    acc = fmaxf(acc, 0.f);
    float* out = (osel == 0) ? g_xa : (osel == 1) ? g_xb : oext;
    out[i] = acc;
}

// ---------------------------------------------------------------------------
// Launch: 4 conv stages (relu; +x relu) x 2 filters, each filter used twice
// ---------------------------------------------------------------------------
extern "C" void kernel_launch(void* const* d_in, const int* in_sizes, int n_in,
                              void* d_out, int out_size) {
    const float* x    = (const float*)d_in[0];   // (2048, 64)
    const float* conn = (const float*)d_in[1];   // (2048, 2048, 12)
    const float* bond = (const float*)d_in[2];   // (2048, 12, 2)
    const float* f0   = (const float*)d_in[3];   // (64, 12, 66)
    const float* f1   = (const float*)d_in[4];   // (64, 12, 66)
    float* out = (float*)d_out;

    prep_g_kernel<<<(2 * D_N * GN + 255) / 256, 256>>>(f0, f1);
    prep_bt_kernel<<<(2 * A_N * D_N + 255) / 256, 256>>>(bond, f0, f1);

    dim3 wgrid(32, 6);
    dim3 bgrid(16, NSPLIT);
    int rblocks = (A_N * D_N + 255) / 256;

    // stage 0: y = relu(conv(x, f0))                -> g_xa
    wgemm_kernel<<<wgrid, 256>>>(x, 2, 0);
    big_gemm_kernel<<<bgrid, 256>>>(conn);
    reduce_kernel<<<rblocks, 256>>>(nullptr, 0, nullptr, 0);

    // stage 1: y = relu(conv(y, f0) + x)            -> g_xb
    wgemm_kernel<<<wgrid, 256>>>(nullptr, 0, 0);
    big_gemm_kernel<<<bgrid, 256>>>(conn);
    reduce_kernel<<<rblocks, 256>>>(x, 0, nullptr, 1);

    // stage 2: y = relu(conv(y, f1))                -> g_xa
    wgemm_kernel<<<wgrid, 256>>>(nullptr, 1, 1);
    big_gemm_kernel<<<bgrid, 256>>>(conn);
    reduce_kernel<<<rblocks, 256>>>(nullptr, 1, nullptr, 0);

    // stage 3: y = relu(conv(y, f1) + x)            -> d_out
    wgemm_kernel<<<wgrid, 256>>>(nullptr, 0, 1);
    big_gemm_kernel<<<bgrid, 256>>>(conn);
    reduce_kernel<<<rblocks, 256>>>(x, 1, out, 2);
}